// round 15
// baseline (speedup 1.0000x reference)
#include <cuda_runtime.h>
#include <cuda_fp16.h>

#define NMAX   100000
#define EMAX   1600000
#define NGRAPH 64
#define NFEAT  128
#define NHID   64
#define NCLASS 10
#define SCAN_B 512

// ---- scratch (allocation-free rule: __device__ globals) ----
__device__ int   g_csrc[EMAX];          // CSR: src ids grouped by dst
__device__ int   g_ecnt[NMAX];          // in-degree (edges only); reset by scanC
__device__ int   g_off[NMAX + 1];       // CSR row offsets (+ sentinel)
__device__ int   g_cursor[NMAX];
__device__ int   g_scan[NMAX];
__device__ int   g_bsum[256];
__device__ int   g_boff[256];
__device__ float g_dinv[NMAX];
__device__ alignas(16) __half g_hs16[(size_t)NMAX * NHID];  // gemm out (gather src)
__device__ alignas(16) __half g_in16[(size_t)NMAX * NHID];  // agg out  (gemm in)
__device__ float g_gsum[NGRAPH * NHID];
__device__ int   g_gcnt[NGRAPH];

union H8I4 { int4 i; __half2 h[4]; };
union H4U2 { uint2 u; __half2 h[2]; };
union H2U  { unsigned u; __half2 h; };

__device__ __forceinline__ unsigned smem_u32(const void* p) {
    unsigned r;
    asm("{ .reg .u64 t; cvta.to.shared.u64 t, %1; cvt.u32.u64 %0, t; }"
        : "=r"(r) : "l"(p));
    return r;
}

// ---------------------------------------------------------------------------
// Histogram in-degree; 4 edges per thread via int4 loads (MLP + fewer insts).
__global__ void k_edge_prep(const int* __restrict__ ei, int E, int N) {
    int t = blockIdx.x * blockDim.x + threadIdx.x;
    int e4 = t * 4;
    if (e4 + 4 <= E && (E & 3) == 0) {
        int4 dd = *reinterpret_cast<const int4*>(ei + E + e4);
        if ((unsigned)dd.x < (unsigned)N) atomicAdd(&g_ecnt[dd.x], 1);
        if ((unsigned)dd.y < (unsigned)N) atomicAdd(&g_ecnt[dd.y], 1);
        if ((unsigned)dd.z < (unsigned)N) atomicAdd(&g_ecnt[dd.z], 1);
        if ((unsigned)dd.w < (unsigned)N) atomicAdd(&g_ecnt[dd.w], 1);
    } else {
        for (int e = e4; e < E && e < e4 + 4; e++) {
            int d = ei[E + e];
            if ((unsigned)d < (unsigned)N) atomicAdd(&g_ecnt[d], 1);
        }
    }
}

// ---- 3-kernel exclusive scan of g_ecnt -> g_off -------------------------
__device__ __forceinline__ int block_incl_scan(int v, int tid) {
    __shared__ int wsum[16];
    int lane = tid & 31, w = tid >> 5;
    int x = v;
#pragma unroll
    for (int o = 1; o < 32; o <<= 1) {
        int t = __shfl_up_sync(0xffffffffu, x, o);
        if (lane >= o) x += t;
    }
    if (lane == 31) wsum[w] = x;
    __syncthreads();
    if (w == 0) {
        int y = (lane < (blockDim.x >> 5)) ? wsum[lane] : 0;
#pragma unroll
        for (int o = 1; o < 16; o <<= 1) {
            int t = __shfl_up_sync(0xffffffffu, y, o);
            if (lane >= o) y += t;
        }
        if (lane < 16) wsum[lane] = y;
    }
    __syncthreads();
    return x + (w > 0 ? wsum[w - 1] : 0);
}

__global__ void k_scanA(int N) {
    int i = blockIdx.x * SCAN_B + threadIdx.x;
    int v = (i < N) ? g_ecnt[i] : 0;
    int incl = block_incl_scan(v, threadIdx.x);
    if (i < N) g_scan[i] = incl - v;
    if (threadIdx.x == SCAN_B - 1) g_bsum[blockIdx.x] = incl;
}

// scanB also zeroes the pool accumulators.
__global__ void k_scanB(int nb) {
    int t = threadIdx.x;
    int v = (t < nb) ? g_bsum[t] : 0;
    int incl = block_incl_scan(v, t);
    if (t < 256) g_boff[t] = incl - v;
    for (int i = t; i < NGRAPH * NHID; i += 256) g_gsum[i] = 0.f;
    if (t < NGRAPH) g_gcnt[t] = 0;
}

// scanC: offsets + dinv + sentinel; resets ecnt for the next graph replay.
__global__ void k_scanC(int N) {
    int i = blockIdx.x * SCAN_B + threadIdx.x;
    if (i >= N) return;
    int off = g_scan[i] + g_boff[blockIdx.x];
    int cnt = g_ecnt[i];
    g_off[i] = off;
    g_cursor[i] = off;
    g_dinv[i] = rsqrtf((float)(cnt + 1));   // +1 self-loop
    g_ecnt[i] = 0;                          // reset for next run
    if (i == N - 1) g_off[N] = off + cnt;
}

// CSR fill; 4 edges per thread via int4 loads of src and dst.
__global__ void k_csr_fill(const int* __restrict__ ei, int E, int N) {
    int t = blockIdx.x * blockDim.x + threadIdx.x;
    int e4 = t * 4;
    if (e4 + 4 <= E && (E & 3) == 0) {
        int4 ss = *reinterpret_cast<const int4*>(ei + e4);
        int4 dd = *reinterpret_cast<const int4*>(ei + E + e4);
        if ((unsigned)ss.x < (unsigned)N && (unsigned)dd.x < (unsigned)N)
            g_csrc[atomicAdd(&g_cursor[dd.x], 1)] = ss.x;
        if ((unsigned)ss.y < (unsigned)N && (unsigned)dd.y < (unsigned)N)
            g_csrc[atomicAdd(&g_cursor[dd.y], 1)] = ss.y;
        if ((unsigned)ss.z < (unsigned)N && (unsigned)dd.z < (unsigned)N)
            g_csrc[atomicAdd(&g_cursor[dd.z], 1)] = ss.z;
        if ((unsigned)ss.w < (unsigned)N && (unsigned)dd.w < (unsigned)N)
            g_csrc[atomicAdd(&g_cursor[dd.w], 1)] = ss.w;
    } else {
        for (int e = e4; e < E && e < e4 + 4; e++) {
            int s = ei[e];
            int d = ei[E + e];
            if ((unsigned)s >= (unsigned)N || (unsigned)d >= (unsigned)N) continue;
            g_csrc[atomicAdd(&g_cursor[d], 1)] = s;
        }
    }
}

// ---------------------------------------------------------------------------
// Layer 1 GEMM via HMMA (m16n8k16, fp16 in / fp32 acc):
//   hs16[n] = fp16(dinv[n] * (x[n] @ W1)).
#define XS_LD 136   // 128 + 8 halves
#define WS_LD 72    // 64 + 8 halves
__global__ void k_gemm1(const float* __restrict__ x, const float* __restrict__ W, int N) {
    __shared__ __half xs[64 * XS_LD];    // 17408 B
    __shared__ __half ws[NFEAT * WS_LD]; // 18432 B
    int tid = threadIdx.x;
    int nb = blockIdx.x * 64;
    const float4* x4 = reinterpret_cast<const float4*>(x);
    const float4* W4 = reinterpret_cast<const float4*>(W);

    for (int i = tid; i < NFEAT * 16; i += 128) {
        int k = i >> 4, c4 = i & 15;
        float4 v = W4[i];
        H4U2 u;
        u.h[0] = __floats2half2_rn(v.x, v.y);
        u.h[1] = __floats2half2_rn(v.z, v.w);
        *reinterpret_cast<uint2*>(&ws[k * WS_LD + c4 * 4]) = u.u;
    }
    for (int i = tid; i < 64 * 32; i += 128) {
        int n = i >> 5, c4 = i & 31;
        float4 v = (nb + n < N) ? x4[(size_t)(nb + n) * 32 + c4]
                                : make_float4(0.f, 0.f, 0.f, 0.f);
        H4U2 u;
        u.h[0] = __floats2half2_rn(v.x, v.y);
        u.h[1] = __floats2half2_rn(v.z, v.w);
        *reinterpret_cast<uint2*>(&xs[n * XS_LD + c4 * 4]) = u.u;
    }
    __syncthreads();

    int lane = tid & 31, warp = tid >> 5;
    int m0 = warp * 16;
    int g = lane >> 2, t = lane & 3;
    float c[8][4];
#pragma unroll
    for (int nt = 0; nt < 8; nt++)
#pragma unroll
        for (int r = 0; r < 4; r++) c[nt][r] = 0.f;

    unsigned xs_base = smem_u32(xs);
    unsigned ws_base = smem_u32(ws);
    int aRow = m0 + (lane & 15);
    int aHalf = lane >> 4;

#pragma unroll
    for (int ks = 0; ks < 8; ks++) {
        unsigned aAddr = xs_base + (unsigned)((aRow * XS_LD + ks * 16 + aHalf * 8) * 2);
        unsigned a0, a1, a2, a3;
        asm volatile("ldmatrix.sync.aligned.m8n8.x4.shared.b16 {%0,%1,%2,%3}, [%4];"
                     : "=r"(a0), "=r"(a1), "=r"(a2), "=r"(a3) : "r"(aAddr));
        int bRow = ks * 16 + (lane & 15);
#pragma unroll
        for (int nt = 0; nt < 8; nt++) {
            unsigned bAddr = ws_base + (unsigned)((bRow * WS_LD + nt * 8) * 2);
            unsigned b0, b1;
            asm volatile("ldmatrix.sync.aligned.m8n8.x2.trans.shared.b16 {%0,%1}, [%2];"
                         : "=r"(b0), "=r"(b1) : "r"(bAddr));
            asm volatile(
                "mma.sync.aligned.m16n8k16.row.col.f32.f16.f16.f32 "
                "{%0,%1,%2,%3}, {%4,%5,%6,%7}, {%8,%9}, {%0,%1,%2,%3};"
                : "+f"(c[nt][0]), "+f"(c[nt][1]), "+f"(c[nt][2]), "+f"(c[nt][3])
                : "r"(a0), "r"(a1), "r"(a2), "r"(a3), "r"(b0), "r"(b1));
        }
    }

    int row0 = nb + m0 + g;
    int row1 = row0 + 8;
    float dv0 = (row0 < N) ? g_dinv[row0] : 0.f;
    float dv1 = (row1 < N) ? g_dinv[row1] : 0.f;
    unsigned* hsu = reinterpret_cast<unsigned*>(g_hs16);
#pragma unroll
    for (int nt = 0; nt < 8; nt++) {
        if (row0 < N) {
            H2U u; u.h = __floats2half2_rn(c[nt][0] * dv0, c[nt][1] * dv0);
            hsu[(size_t)row0 * 32 + nt * 4 + t] = u.u;
        }
        if (row1 < N) {
            H2U u; u.h = __floats2half2_rn(c[nt][2] * dv1, c[nt][3] * dv1);
            hsu[(size_t)row1 * 32 + nt * 4 + t] = u.u;
        }
    }
}

// ---------------------------------------------------------------------------
// Layers 2/3 GEMM via HMMA (K = 64): input = g_in16 (already relu'd fp16);
// hs16 = fp16(dinv * (in @ W)).
#define XS2_LD 72   // 64 + 8 halves
__global__ void k_gemm23(const float* __restrict__ W, int N) {
    __shared__ __half xs[64 * XS2_LD];   // 9216 B
    __shared__ __half ws[NHID * WS_LD];  // 9216 B
    int tid = threadIdx.x;
    int nb = blockIdx.x * 64;
    const float4* W4 = reinterpret_cast<const float4*>(W);
    const int4* in4 = reinterpret_cast<const int4*>(g_in16);

    for (int i = tid; i < NHID * 16; i += 128) {
        int k = i >> 4, c4 = i & 15;
        float4 v = W4[i];
        H4U2 u;
        u.h[0] = __floats2half2_rn(v.x, v.y);
        u.h[1] = __floats2half2_rn(v.z, v.w);
        *reinterpret_cast<uint2*>(&ws[k * WS_LD + c4 * 4]) = u.u;
    }
    for (int i = tid; i < 64 * 8; i += 128) {
        int n = i >> 3, c8 = i & 7;
        int4 v = (nb + n < N) ? in4[(size_t)(nb + n) * 8 + c8]
                              : make_int4(0, 0, 0, 0);
        *reinterpret_cast<int4*>(&xs[n * XS2_LD + c8 * 8]) = v;
    }
    __syncthreads();

    int lane = tid & 31, warp = tid >> 5;
    int m0 = warp * 16;
    int g = lane >> 2, t = lane & 3;
    float c[8][4];
#pragma unroll
    for (int nt = 0; nt < 8; nt++)
#pragma unroll
        for (int r = 0; r < 4; r++) c[nt][r] = 0.f;

    unsigned xs_base = smem_u32(xs);
    unsigned ws_base = smem_u32(ws);
    int aRow = m0 + (lane & 15);
    int aHalf = lane >> 4;

#pragma unroll
    for (int ks = 0; ks < 4; ks++) {
        unsigned aAddr = xs_base + (unsigned)((aRow * XS2_LD + ks * 16 + aHalf * 8) * 2);
        unsigned a0, a1, a2, a3;
        asm volatile("ldmatrix.sync.aligned.m8n8.x4.shared.b16 {%0,%1,%2,%3}, [%4];"
                     : "=r"(a0), "=r"(a1), "=r"(a2), "=r"(a3) : "r"(aAddr));
        int bRow = ks * 16 + (lane & 15);
#pragma unroll
        for (int nt = 0; nt < 8; nt++) {
            unsigned bAddr = ws_base + (unsigned)((bRow * WS_LD + nt * 8) * 2);
            unsigned b0, b1;
            asm volatile("ldmatrix.sync.aligned.m8n8.x2.trans.shared.b16 {%0,%1}, [%2];"
                         : "=r"(b0), "=r"(b1) : "r"(bAddr));
            asm volatile(
                "mma.sync.aligned.m16n8k16.row.col.f32.f16.f16.f32 "
                "{%0,%1,%2,%3}, {%4,%5,%6,%7}, {%8,%9}, {%0,%1,%2,%3};"
                : "+f"(c[nt][0]), "+f"(c[nt][1]), "+f"(c[nt][2]), "+f"(c[nt][3])
                : "r"(a0), "r"(a1), "r"(a2), "r"(a3), "r"(b0), "r"(b1));
        }
    }

    int row0 = nb + m0 + g;
    int row1 = row0 + 8;
    float dv0 = (row0 < N) ? g_dinv[row0] : 0.f;
    float dv1 = (row1 < N) ? g_dinv[row1] : 0.f;
    unsigned* hsu = reinterpret_cast<unsigned*>(g_hs16);
#pragma unroll
    for (int nt = 0; nt < 8; nt++) {
        if (row0 < N) {
            H2U u; u.h = __floats2half2_rn(c[nt][0] * dv0, c[nt][1] * dv0);
            hsu[(size_t)row0 * 32 + nt * 4 + t] = u.u;
        }
        if (row1 < N) {
            H2U u; u.h = __floats2half2_rn(c[nt][2] * dv1, c[nt][3] * dv1);
            hsu[(size_t)row1 * 32 + nt * 4 + t] = u.u;
        }
    }
}

// ---------------------------------------------------------------------------
// CSR gather aggregation + fused next-layer input transform (R13 shape):
// one warp per node; 8 lanes x 16B cover the 128B row; 4 edge slots, x2 unroll.
//   sum = hs[n] + sum_{s in in(n)} hs[s]   (fp16 HADD2 slots, fp32 reduce)
//   in16[n][c] = fp16(relu(dinv[n]*sum[c] + bias[c]))
__global__ void k_agg(const float* __restrict__ bias, int N) {
    int warp = (blockIdx.x * blockDim.x + threadIdx.x) >> 5;
    if (warp >= N) return;
    int lane = threadIdx.x & 31;
    int p = lane & 7;        // 16B chunk (cols p*8 .. p*8+7)
    int q = lane >> 3;       // edge slot 0..3
    const int4* h16 = reinterpret_cast<const int4*>(g_hs16);
    const int* __restrict__ csrc = g_csrc;
    int n = warp;
    int start = g_off[n];
    int end = g_off[n + 1];

    __half2 a[4];
    if (q == 0) {            // self-loop init
        H8I4 v; v.i = h16[(size_t)n * 8 + p];
#pragma unroll
        for (int i = 0; i < 4; i++) a[i] = v.h[i];
    } else {
#pragma unroll
        for (int i = 0; i < 4; i++) a[i] = __half2half2(__ushort_as_half(0));
    }
    int j = start + q;
    for (; j + 4 < end; j += 8) {
        int sA = csrc[j];
        int sB = csrc[j + 4];
        H8I4 vA; vA.i = h16[(size_t)sA * 8 + p];
        H8I4 vB; vB.i = h16[(size_t)sB * 8 + p];
#pragma unroll
        for (int i = 0; i < 4; i++) a[i] = __hadd2(a[i], vA.h[i]);
#pragma unroll
        for (int i = 0; i < 4; i++) a[i] = __hadd2(a[i], vB.h[i]);
    }
    if (j < end) {
        int s = csrc[j];
        H8I4 v; v.i = h16[(size_t)s * 8 + p];
#pragma unroll
        for (int i = 0; i < 4; i++) a[i] = __hadd2(a[i], v.h[i]);
    }
    float f[8];
#pragma unroll
    for (int i = 0; i < 4; i++) {
        float2 t = __half22float2(a[i]);
        f[2 * i] = t.x; f[2 * i + 1] = t.y;
    }
    const unsigned F = 0xffffffffu;
#pragma unroll
    for (int off = 8; off <= 16; off <<= 1) {
#pragma unroll
        for (int i = 0; i < 8; i++) f[i] += __shfl_xor_sync(F, f[i], off);
    }
    if (lane < 8) {
        // fused epilogue: relu(dinv*sum + b) -> fp16
        const float4* b4 = reinterpret_cast<const float4*>(bias);
        float4 bb0 = b4[lane * 2];
        float4 bb1 = b4[lane * 2 + 1];
        float dv = g_dinv[n];
        float v0 = fmaxf(fmaf(dv, f[0], bb0.x), 0.f);
        float v1 = fmaxf(fmaf(dv, f[1], bb0.y), 0.f);
        float v2 = fmaxf(fmaf(dv, f[2], bb0.z), 0.f);
        float v3 = fmaxf(fmaf(dv, f[3], bb0.w), 0.f);
        float v4 = fmaxf(fmaf(dv, f[4], bb1.x), 0.f);
        float v5 = fmaxf(fmaf(dv, f[5], bb1.y), 0.f);
        float v6 = fmaxf(fmaf(dv, f[6], bb1.z), 0.f);
        float v7 = fmaxf(fmaf(dv, f[7], bb1.w), 0.f);
        H8I4 o;
        o.h[0] = __floats2half2_rn(v0, v1);
        o.h[1] = __floats2half2_rn(v2, v3);
        o.h[2] = __floats2half2_rn(v4, v5);
        o.h[3] = __floats2half2_rn(v6, v7);
        reinterpret_cast<int4*>(g_in16)[(size_t)n * 8 + lane] = o.i;
    }
}

// ---------------------------------------------------------------------------
// Pool: segment-sum of g_in16 (already relu'd); 4-node run-length batching.
__global__ void k_pool(const int* __restrict__ batch, int N) {
    int t = blockIdx.x * blockDim.x + threadIdx.x;
    int c2 = t & 31;              // half2 col index (cols 2*c2, 2*c2+1)
    int n0 = (t >> 5) * 4;
    if (n0 >= N) return;
    const __half2* in2 = reinterpret_cast<const __half2*>(g_in16);
    float ax = 0.f, ay = 0.f;
    int cnt = 0;
    int gprev = -1;
    for (int j = 0; j < 4; j++) {
        int n = n0 + j;
        if (n >= N) break;
        int g = batch[n];
        if ((unsigned)g >= NGRAPH) continue;
        if (g != gprev) {
            if (gprev >= 0) {
                atomicAdd(&g_gsum[gprev * NHID + c2 * 2], ax);
                atomicAdd(&g_gsum[gprev * NHID + c2 * 2 + 1], ay);
                if (c2 == 0) atomicAdd(&g_gcnt[gprev], cnt);
            }
            ax = 0.f; ay = 0.f; cnt = 0; gprev = g;
        }
        float2 f = __half22float2(in2[(size_t)n * 32 + c2]);
        ax += f.x; ay += f.y; cnt++;
    }
    if (gprev >= 0) {
        atomicAdd(&g_gsum[gprev * NHID + c2 * 2], ax);
        atomicAdd(&g_gsum[gprev * NHID + c2 * 2 + 1], ay);
        if (c2 == 0) atomicAdd(&g_gcnt[gprev], cnt);
    }
}

__global__ void k_head(const float* __restrict__ Wl, const float* __restrict__ bl,
                       float* __restrict__ out) {
    int g = threadIdx.x;
    if (g >= NGRAPH) return;
    float cnt = fmaxf((float)g_gcnt[g], 1.f);
    float inv = 1.f / cnt;
    float l[NCLASS];
#pragma unroll
    for (int c = 0; c < NCLASS; c++) l[c] = bl[c];
    for (int k = 0; k < NHID; k++) {
        float p = g_gsum[g * NHID + k] * inv;
#pragma unroll
        for (int c = 0; c < NCLASS; c++) l[c] = fmaf(p, Wl[k * NCLASS + c], l[c]);
    }
    float m = l[0];
#pragma unroll
    for (int c = 1; c < NCLASS; c++) m = fmaxf(m, l[c]);
    float s = 0.f;
#pragma unroll
    for (int c = 0; c < NCLASS; c++) { l[c] = __expf(l[c] - m); s += l[c]; }
    float is = 1.f / s;
#pragma unroll
    for (int c = 0; c < NCLASS; c++) out[g * NCLASS + c] = l[c] * is;
}

// ---------------------------------------------------------------------------
extern "C" void kernel_launch(void* const* d_in, const int* in_sizes, int n_in,
                              void* d_out, int out_size) {
    const float* x     = (const float*)d_in[0];
    const int*   ei    = (const int*)d_in[1];
    const int*   batch = (const int*)d_in[2];
    const float* W1 = (const float*)d_in[3];
    const float* b1 = (const float*)d_in[4];
    const float* W2 = (const float*)d_in[5];
    const float* b2 = (const float*)d_in[6];
    const float* W3 = (const float*)d_in[7];
    const float* b3 = (const float*)d_in[8];
    const float* Wl = (const float*)d_in[9];
    const float* bl = (const float*)d_in[10];
    float* out = (float*)d_out;

    int N = in_sizes[0] / NFEAT;
    int E = in_sizes[1] / 2;

    const int T = 256;
    int nScanBlocks = (N + SCAN_B - 1) / SCAN_B;
    int E4 = (E + 3) / 4;

    k_edge_prep<<<(E4 + T - 1) / T, T>>>(ei, E, N);
    k_scanA<<<nScanBlocks, SCAN_B>>>(N);
    k_scanB<<<1, 256>>>(nScanBlocks);
    k_scanC<<<nScanBlocks, SCAN_B>>>(N);
    k_csr_fill<<<(E4 + T - 1) / T, T>>>(ei, E, N);

    int gemmBlocks = (N + 63) / 64;
    int aggBlocks = (N * 32 + T - 1) / T;

    // Layer 1 (HMMA, K=128)
    k_gemm1<<<gemmBlocks, 128>>>(x, W1, N);
    k_agg<<<aggBlocks, T>>>(b1, N);
    // Layer 2 (HMMA, K=64)
    k_gemm23<<<gemmBlocks, 128>>>(W2, N);
    k_agg<<<aggBlocks, T>>>(b2, N);
    // Layer 3 (HMMA, K=64)
    k_gemm23<<<gemmBlocks, 128>>>(W3, N);
    k_agg<<<aggBlocks, T>>>(b3, N);

    // Pool + head
    k_pool<<<(((N + 3) / 4) * 32 + T - 1) / T, T>>>(batch, N);
    k_head<<<1, 64>>>(Wl, bl, out);
}

// round 16
// speedup vs baseline: 1.3481x; 1.3481x over previous
#include <cuda_runtime.h>
#include <cuda_fp16.h>

#define NMAX   100000
#define EMAX   1600000
#define NGRAPH 64
#define NFEAT  128
#define NHID   64
#define NCLASS 10
#define SCAN_B 512

// ---- scratch (allocation-free rule: __device__ globals) ----
__device__ int   g_csrc[EMAX];          // CSR: src ids grouped by dst
__device__ int   g_ecnt[NMAX];          // in-degree (edges only); reset by scanC
__device__ int   g_off[NMAX + 1];       // CSR row offsets (+ sentinel)
__device__ int   g_cursor[NMAX];
__device__ int   g_scan[NMAX];
__device__ int   g_bsum[256];
__device__ int   g_boff[256];
__device__ float g_dinv[NMAX];
__device__ alignas(16) __half g_hs16[(size_t)NMAX * NHID];  // gemm out (gather src)
__device__ alignas(16) __half g_in16[(size_t)NMAX * NHID];  // agg out  (gemm in)
__device__ float g_gsum[NGRAPH * NHID];
__device__ int   g_gcnt[NGRAPH];

union H8I4 { int4 i; __half2 h[4]; };
union H4U2 { uint2 u; __half2 h[2]; };
union H2U  { unsigned u; __half2 h; };

__device__ __forceinline__ unsigned smem_u32(const void* p) {
    unsigned r;
    asm("{ .reg .u64 t; cvta.to.shared.u64 t, %1; cvt.u32.u64 %0, t; }"
        : "=r"(r) : "l"(p));
    return r;
}

// ---------------------------------------------------------------------------
__global__ void k_edge_prep(const int* __restrict__ ei, int E, int N) {
    int e = blockIdx.x * blockDim.x + threadIdx.x;
    if (e >= E) return;
    int s = ei[e];
    int d = ei[E + e];
    if ((unsigned)s >= (unsigned)N || (unsigned)d >= (unsigned)N) return;
    atomicAdd(&g_ecnt[d], 1);
}

// ---- 3-kernel exclusive scan of g_ecnt -> g_off -------------------------
__device__ __forceinline__ int block_incl_scan(int v, int tid) {
    __shared__ int wsum[16];
    int lane = tid & 31, w = tid >> 5;
    int x = v;
#pragma unroll
    for (int o = 1; o < 32; o <<= 1) {
        int t = __shfl_up_sync(0xffffffffu, x, o);
        if (lane >= o) x += t;
    }
    if (lane == 31) wsum[w] = x;
    __syncthreads();
    if (w == 0) {
        int y = (lane < (blockDim.x >> 5)) ? wsum[lane] : 0;
#pragma unroll
        for (int o = 1; o < 16; o <<= 1) {
            int t = __shfl_up_sync(0xffffffffu, y, o);
            if (lane >= o) y += t;
        }
        if (lane < 16) wsum[lane] = y;
    }
    __syncthreads();
    return x + (w > 0 ? wsum[w - 1] : 0);
}

__global__ void k_scanA(int N) {
    int i = blockIdx.x * SCAN_B + threadIdx.x;
    int v = (i < N) ? g_ecnt[i] : 0;
    int incl = block_incl_scan(v, threadIdx.x);
    if (i < N) g_scan[i] = incl - v;
    if (threadIdx.x == SCAN_B - 1) g_bsum[blockIdx.x] = incl;
}

// scanB also zeroes the pool accumulators.
__global__ void k_scanB(int nb) {
    int t = threadIdx.x;
    int v = (t < nb) ? g_bsum[t] : 0;
    int incl = block_incl_scan(v, t);
    if (t < 256) g_boff[t] = incl - v;
    for (int i = t; i < NGRAPH * NHID; i += 256) g_gsum[i] = 0.f;
    if (t < NGRAPH) g_gcnt[t] = 0;
}

// scanC: offsets + dinv + sentinel; resets ecnt for the next graph replay.
__global__ void k_scanC(int N) {
    int i = blockIdx.x * SCAN_B + threadIdx.x;
    if (i >= N) return;
    int off = g_scan[i] + g_boff[blockIdx.x];
    int cnt = g_ecnt[i];
    g_off[i] = off;
    g_cursor[i] = off;
    g_dinv[i] = rsqrtf((float)(cnt + 1));   // +1 self-loop
    g_ecnt[i] = 0;                          // reset for next run
    if (i == N - 1) g_off[N] = off + cnt;
}

__global__ void k_csr_fill(const int* __restrict__ ei, int E, int N) {
    int e = blockIdx.x * blockDim.x + threadIdx.x;
    if (e >= E) return;
    int s = ei[e];
    int d = ei[E + e];
    if ((unsigned)s >= (unsigned)N || (unsigned)d >= (unsigned)N) return;
    int pos = atomicAdd(&g_cursor[d], 1);
    g_csrc[pos] = s;
}

// ---------------------------------------------------------------------------
// Layer 1 GEMM via HMMA (m16n8k16, fp16 in / fp32 acc):
//   hs16[n] = fp16(dinv[n] * (x[n] @ W1)).
#define XS_LD 136   // 128 + 8 halves
#define WS_LD 72    // 64 + 8 halves
__global__ void k_gemm1(const float* __restrict__ x, const float* __restrict__ W, int N) {
    __shared__ __half xs[64 * XS_LD];    // 17408 B
    __shared__ __half ws[NFEAT * WS_LD]; // 18432 B
    int tid = threadIdx.x;
    int nb = blockIdx.x * 64;
    const float4* x4 = reinterpret_cast<const float4*>(x);
    const float4* W4 = reinterpret_cast<const float4*>(W);

    for (int i = tid; i < NFEAT * 16; i += 128) {
        int k = i >> 4, c4 = i & 15;
        float4 v = W4[i];
        H4U2 u;
        u.h[0] = __floats2half2_rn(v.x, v.y);
        u.h[1] = __floats2half2_rn(v.z, v.w);
        *reinterpret_cast<uint2*>(&ws[k * WS_LD + c4 * 4]) = u.u;
    }
    for (int i = tid; i < 64 * 32; i += 128) {
        int n = i >> 5, c4 = i & 31;
        float4 v = (nb + n < N) ? x4[(size_t)(nb + n) * 32 + c4]
                                : make_float4(0.f, 0.f, 0.f, 0.f);
        H4U2 u;
        u.h[0] = __floats2half2_rn(v.x, v.y);
        u.h[1] = __floats2half2_rn(v.z, v.w);
        *reinterpret_cast<uint2*>(&xs[n * XS_LD + c4 * 4]) = u.u;
    }
    __syncthreads();

    int lane = tid & 31, warp = tid >> 5;
    int m0 = warp * 16;
    int g = lane >> 2, t = lane & 3;
    float c[8][4];
#pragma unroll
    for (int nt = 0; nt < 8; nt++)
#pragma unroll
        for (int r = 0; r < 4; r++) c[nt][r] = 0.f;

    unsigned xs_base = smem_u32(xs);
    unsigned ws_base = smem_u32(ws);
    int aRow = m0 + (lane & 15);
    int aHalf = lane >> 4;

#pragma unroll
    for (int ks = 0; ks < 8; ks++) {
        unsigned aAddr = xs_base + (unsigned)((aRow * XS_LD + ks * 16 + aHalf * 8) * 2);
        unsigned a0, a1, a2, a3;
        asm volatile("ldmatrix.sync.aligned.m8n8.x4.shared.b16 {%0,%1,%2,%3}, [%4];"
                     : "=r"(a0), "=r"(a1), "=r"(a2), "=r"(a3) : "r"(aAddr));
        int bRow = ks * 16 + (lane & 15);
#pragma unroll
        for (int nt = 0; nt < 8; nt++) {
            unsigned bAddr = ws_base + (unsigned)((bRow * WS_LD + nt * 8) * 2);
            unsigned b0, b1;
            asm volatile("ldmatrix.sync.aligned.m8n8.x2.trans.shared.b16 {%0,%1}, [%2];"
                         : "=r"(b0), "=r"(b1) : "r"(bAddr));
            asm volatile(
                "mma.sync.aligned.m16n8k16.row.col.f32.f16.f16.f32 "
                "{%0,%1,%2,%3}, {%4,%5,%6,%7}, {%8,%9}, {%0,%1,%2,%3};"
                : "+f"(c[nt][0]), "+f"(c[nt][1]), "+f"(c[nt][2]), "+f"(c[nt][3])
                : "r"(a0), "r"(a1), "r"(a2), "r"(a3), "r"(b0), "r"(b1));
        }
    }

    int row0 = nb + m0 + g;
    int row1 = row0 + 8;
    float dv0 = (row0 < N) ? g_dinv[row0] : 0.f;
    float dv1 = (row1 < N) ? g_dinv[row1] : 0.f;
    unsigned* hsu = reinterpret_cast<unsigned*>(g_hs16);
#pragma unroll
    for (int nt = 0; nt < 8; nt++) {
        if (row0 < N) {
            H2U u; u.h = __floats2half2_rn(c[nt][0] * dv0, c[nt][1] * dv0);
            hsu[(size_t)row0 * 32 + nt * 4 + t] = u.u;
        }
        if (row1 < N) {
            H2U u; u.h = __floats2half2_rn(c[nt][2] * dv1, c[nt][3] * dv1);
            hsu[(size_t)row1 * 32 + nt * 4 + t] = u.u;
        }
    }
}

// ---------------------------------------------------------------------------
// Layers 2/3 GEMM via HMMA (K = 64): input = g_in16 (already relu'd fp16);
// hs16 = fp16(dinv * (in @ W)).
#define XS2_LD 72   // 64 + 8 halves
__global__ void k_gemm23(const float* __restrict__ W, int N) {
    __shared__ __half xs[64 * XS2_LD];   // 9216 B
    __shared__ __half ws[NHID * WS_LD];  // 9216 B
    int tid = threadIdx.x;
    int nb = blockIdx.x * 64;
    const float4* W4 = reinterpret_cast<const float4*>(W);
    const int4* in4 = reinterpret_cast<const int4*>(g_in16);

    for (int i = tid; i < NHID * 16; i += 128) {
        int k = i >> 4, c4 = i & 15;
        float4 v = W4[i];
        H4U2 u;
        u.h[0] = __floats2half2_rn(v.x, v.y);
        u.h[1] = __floats2half2_rn(v.z, v.w);
        *reinterpret_cast<uint2*>(&ws[k * WS_LD + c4 * 4]) = u.u;
    }
    for (int i = tid; i < 64 * 8; i += 128) {
        int n = i >> 3, c8 = i & 7;
        int4 v = (nb + n < N) ? in4[(size_t)(nb + n) * 8 + c8]
                              : make_int4(0, 0, 0, 0);
        *reinterpret_cast<int4*>(&xs[n * XS2_LD + c8 * 8]) = v;
    }
    __syncthreads();

    int lane = tid & 31, warp = tid >> 5;
    int m0 = warp * 16;
    int g = lane >> 2, t = lane & 3;
    float c[8][4];
#pragma unroll
    for (int nt = 0; nt < 8; nt++)
#pragma unroll
        for (int r = 0; r < 4; r++) c[nt][r] = 0.f;

    unsigned xs_base = smem_u32(xs);
    unsigned ws_base = smem_u32(ws);
    int aRow = m0 + (lane & 15);
    int aHalf = lane >> 4;

#pragma unroll
    for (int ks = 0; ks < 4; ks++) {
        unsigned aAddr = xs_base + (unsigned)((aRow * XS2_LD + ks * 16 + aHalf * 8) * 2);
        unsigned a0, a1, a2, a3;
        asm volatile("ldmatrix.sync.aligned.m8n8.x4.shared.b16 {%0,%1,%2,%3}, [%4];"
                     : "=r"(a0), "=r"(a1), "=r"(a2), "=r"(a3) : "r"(aAddr));
        int bRow = ks * 16 + (lane & 15);
#pragma unroll
        for (int nt = 0; nt < 8; nt++) {
            unsigned bAddr = ws_base + (unsigned)((bRow * WS_LD + nt * 8) * 2);
            unsigned b0, b1;
            asm volatile("ldmatrix.sync.aligned.m8n8.x2.trans.shared.b16 {%0,%1}, [%2];"
                         : "=r"(b0), "=r"(b1) : "r"(bAddr));
            asm volatile(
                "mma.sync.aligned.m16n8k16.row.col.f32.f16.f16.f32 "
                "{%0,%1,%2,%3}, {%4,%5,%6,%7}, {%8,%9}, {%0,%1,%2,%3};"
                : "+f"(c[nt][0]), "+f"(c[nt][1]), "+f"(c[nt][2]), "+f"(c[nt][3])
                : "r"(a0), "r"(a1), "r"(a2), "r"(a3), "r"(b0), "r"(b1));
        }
    }

    int row0 = nb + m0 + g;
    int row1 = row0 + 8;
    float dv0 = (row0 < N) ? g_dinv[row0] : 0.f;
    float dv1 = (row1 < N) ? g_dinv[row1] : 0.f;
    unsigned* hsu = reinterpret_cast<unsigned*>(g_hs16);
#pragma unroll
    for (int nt = 0; nt < 8; nt++) {
        if (row0 < N) {
            H2U u; u.h = __floats2half2_rn(c[nt][0] * dv0, c[nt][1] * dv0);
            hsu[(size_t)row0 * 32 + nt * 4 + t] = u.u;
        }
        if (row1 < N) {
            H2U u; u.h = __floats2half2_rn(c[nt][2] * dv1, c[nt][3] * dv1);
            hsu[(size_t)row1 * 32 + nt * 4 + t] = u.u;
        }
    }
}

// ---------------------------------------------------------------------------
// CSR gather aggregation + fused next-layer input transform:
//   sum = hs[n] + sum_{s in in(n)} hs[s]   (fp16 HADD2 slots, fp32 reduce)
//   in16[n][c] = fp16(relu(dinv[n]*sum[c] + bias[c]))
__global__ void k_agg(const float* __restrict__ bias, int N) {
    int warp = (blockIdx.x * blockDim.x + threadIdx.x) >> 5;
    if (warp >= N) return;
    int lane = threadIdx.x & 31;
    int p = lane & 7;        // 16B chunk (cols p*8 .. p*8+7)
    int q = lane >> 3;       // edge slot 0..3
    const int4* h16 = reinterpret_cast<const int4*>(g_hs16);
    const int* __restrict__ csrc = g_csrc;
    int n = warp;
    int start = g_off[n];
    int end = g_off[n + 1];

    __half2 a[4];
    if (q == 0) {            // self-loop init
        H8I4 v; v.i = h16[(size_t)n * 8 + p];
#pragma unroll
        for (int i = 0; i < 4; i++) a[i] = v.h[i];
    } else {
#pragma unroll
        for (int i = 0; i < 4; i++) a[i] = __half2half2(__ushort_as_half(0));
    }
    int j = start + q;
    for (; j + 4 < end; j += 8) {
        int sA = csrc[j];
        int sB = csrc[j + 4];
        H8I4 vA; vA.i = h16[(size_t)sA * 8 + p];
        H8I4 vB; vB.i = h16[(size_t)sB * 8 + p];
#pragma unroll
        for (int i = 0; i < 4; i++) a[i] = __hadd2(a[i], vA.h[i]);
#pragma unroll
        for (int i = 0; i < 4; i++) a[i] = __hadd2(a[i], vB.h[i]);
    }
    if (j < end) {
        int s = csrc[j];
        H8I4 v; v.i = h16[(size_t)s * 8 + p];
#pragma unroll
        for (int i = 0; i < 4; i++) a[i] = __hadd2(a[i], v.h[i]);
    }
    float f[8];
#pragma unroll
    for (int i = 0; i < 4; i++) {
        float2 t = __half22float2(a[i]);
        f[2 * i] = t.x; f[2 * i + 1] = t.y;
    }
    const unsigned F = 0xffffffffu;
#pragma unroll
    for (int off = 8; off <= 16; off <<= 1) {
#pragma unroll
        for (int i = 0; i < 8; i++) f[i] += __shfl_xor_sync(F, f[i], off);
    }
    if (lane < 8) {
        // fused epilogue: relu(dinv*sum + b) -> fp16
        const float4* b4 = reinterpret_cast<const float4*>(bias);
        float4 bb0 = b4[lane * 2];
        float4 bb1 = b4[lane * 2 + 1];
        float dv = g_dinv[n];
        float v0 = fmaxf(fmaf(dv, f[0], bb0.x), 0.f);
        float v1 = fmaxf(fmaf(dv, f[1], bb0.y), 0.f);
        float v2 = fmaxf(fmaf(dv, f[2], bb0.z), 0.f);
        float v3 = fmaxf(fmaf(dv, f[3], bb0.w), 0.f);
        float v4 = fmaxf(fmaf(dv, f[4], bb1.x), 0.f);
        float v5 = fmaxf(fmaf(dv, f[5], bb1.y), 0.f);
        float v6 = fmaxf(fmaf(dv, f[6], bb1.z), 0.f);
        float v7 = fmaxf(fmaf(dv, f[7], bb1.w), 0.f);
        H8I4 o;
        o.h[0] = __floats2half2_rn(v0, v1);
        o.h[1] = __floats2half2_rn(v2, v3);
        o.h[2] = __floats2half2_rn(v4, v5);
        o.h[3] = __floats2half2_rn(v6, v7);
        reinterpret_cast<int4*>(g_in16)[(size_t)n * 8 + lane] = o.i;
    }
}

// ---------------------------------------------------------------------------
// Pool: segment-sum of g_in16 (already relu'd); 4-node run-length batching.
__global__ void k_pool(const int* __restrict__ batch, int N) {
    int t = blockIdx.x * blockDim.x + threadIdx.x;
    int c2 = t & 31;              // half2 col index (cols 2*c2, 2*c2+1)
    int n0 = (t >> 5) * 4;
    if (n0 >= N) return;
    const __half2* in2 = reinterpret_cast<const __half2*>(g_in16);
    float ax = 0.f, ay = 0.f;
    int cnt = 0;
    int gprev = -1;
    for (int j = 0; j < 4; j++) {
        int n = n0 + j;
        if (n >= N) break;
        int g = batch[n];
        if ((unsigned)g >= NGRAPH) continue;
        if (g != gprev) {
            if (gprev >= 0) {
                atomicAdd(&g_gsum[gprev * NHID + c2 * 2], ax);
                atomicAdd(&g_gsum[gprev * NHID + c2 * 2 + 1], ay);
                if (c2 == 0) atomicAdd(&g_gcnt[gprev], cnt);
            }
            ax = 0.f; ay = 0.f; cnt = 0; gprev = g;
        }
        float2 f = __half22float2(in2[(size_t)n * 32 + c2]);
        ax += f.x; ay += f.y; cnt++;
    }
    if (gprev >= 0) {
        atomicAdd(&g_gsum[gprev * NHID + c2 * 2], ax);
        atomicAdd(&g_gsum[gprev * NHID + c2 * 2 + 1], ay);
        if (c2 == 0) atomicAdd(&g_gcnt[gprev], cnt);
    }
}

__global__ void k_head(const float* __restrict__ Wl, const float* __restrict__ bl,
                       float* __restrict__ out) {
    int g = threadIdx.x;
    if (g >= NGRAPH) return;
    float cnt = fmaxf((float)g_gcnt[g], 1.f);
    float inv = 1.f / cnt;
    float l[NCLASS];
#pragma unroll
    for (int c = 0; c < NCLASS; c++) l[c] = bl[c];
    for (int k = 0; k < NHID; k++) {
        float p = g_gsum[g * NHID + k] * inv;
#pragma unroll
        for (int c = 0; c < NCLASS; c++) l[c] = fmaf(p, Wl[k * NCLASS + c], l[c]);
    }
    float m = l[0];
#pragma unroll
    for (int c = 1; c < NCLASS; c++) m = fmaxf(m, l[c]);
    float s = 0.f;
#pragma unroll
    for (int c = 0; c < NCLASS; c++) { l[c] = __expf(l[c] - m); s += l[c]; }
    float is = 1.f / s;
#pragma unroll
    for (int c = 0; c < NCLASS; c++) out[g * NCLASS + c] = l[c] * is;
}

// ---------------------------------------------------------------------------
extern "C" void kernel_launch(void* const* d_in, const int* in_sizes, int n_in,
                              void* d_out, int out_size) {
    const float* x     = (const float*)d_in[0];
    const int*   ei    = (const int*)d_in[1];
    const int*   batch = (const int*)d_in[2];
    const float* W1 = (const float*)d_in[3];
    const float* b1 = (const float*)d_in[4];
    const float* W2 = (const float*)d_in[5];
    const float* b2 = (const float*)d_in[6];
    const float* W3 = (const float*)d_in[7];
    const float* b3 = (const float*)d_in[8];
    const float* Wl = (const float*)d_in[9];
    const float* bl = (const float*)d_in[10];
    float* out = (float*)d_out;

    int N = in_sizes[0] / NFEAT;
    int E = in_sizes[1] / 2;

    const int T = 256;
    int nScanBlocks = (N + SCAN_B - 1) / SCAN_B;

    k_edge_prep<<<(E + T - 1) / T, T>>>(ei, E, N);
    k_scanA<<<nScanBlocks, SCAN_B>>>(N);
    k_scanB<<<1, 256>>>(nScanBlocks);
    k_scanC<<<nScanBlocks, SCAN_B>>>(N);
    k_csr_fill<<<(E + T - 1) / T, T>>>(ei, E, N);

    int gemmBlocks = (N + 63) / 64;
    int aggBlocks = (N * 32 + T - 1) / T;

    // Layer 1 (HMMA, K=128)
    k_gemm1<<<gemmBlocks, 128>>>(x, W1, N);
    k_agg<<<aggBlocks, T>>>(b1, N);
    // Layer 2 (HMMA, K=64)
    k_gemm23<<<gemmBlocks, 128>>>(W2, N);
    k_agg<<<aggBlocks, T>>>(b2, N);
    // Layer 3 (HMMA, K=64)
    k_gemm23<<<gemmBlocks, 128>>>(W3, N);
    k_agg<<<aggBlocks, T>>>(b3, N);

    // Pool + head
    k_pool<<<(((N + 3) / 4) * 32 + T - 1) / T, T>>>(batch, N);
    k_head<<<1, 64>>>(Wl, bl, out);
}